// round 4
// baseline (speedup 1.0000x reference)
#include <cuda_runtime.h>
#include <cuda_fp16.h>
#include <cstdint>

// Problem constants
#define BATCH   512
#define DIMC    64
#define BOOK    1024
#define EMB     64
#define CWDIM   (DIMC * EMB)            // 4096

// Output layout (floats): cw | one_hot | new_codebook | new_ema
#define CW_OFF    0
#define CW_SIZE   (BATCH * CWDIM)
#define OH_OFF    (CW_OFF + CW_SIZE)
#define OH_SIZE   (BATCH * DIMC * BOOK)              // 33,554,432
#define NCB_OFF   (OH_OFF + OH_SIZE)
#define NCB_SIZE  (DIMC * BOOK * EMB)                // 4,194,304
#define NEMA_OFF  (NCB_OFF + NCB_SIZE)
#define NEMA_SIZE (DIMC * BOOK)

#define TAU 2e-4f

// Scratch: fp16 2-term splits packed [h(64)|l(64)], |c|^2, per-tile top2
__device__ __half g_x2[DIMC][BATCH][128];     // 8.4 MB
__device__ __half g_c2[DIMC][BOOK][128];      // 16.8 MB
__device__ float  g_bsq[DIMC * BOOK];
__device__ float4 g_top[BATCH * DIMC * 8];    // (b1, b2, k1bits, -) per N-tile

static __device__ __forceinline__ uint32_t smem_u32(const void* p) {
    uint32_t a;
    asm("{ .reg .u64 t; cvta.to.shared.u64 t, %1; cvt.u32.u64 %0, t; }"
        : "=r"(a) : "l"(p));
    return a;
}

#define LDSM_X4(r0, r1, r2, r3, a)                                       \
    asm volatile("ldmatrix.sync.aligned.m8n8.x4.shared.b16 "             \
                 "{%0,%1,%2,%3}, [%4];"                                  \
                 : "=r"(r0), "=r"(r1), "=r"(r2), "=r"(r3) : "r"(a))

#define MMA16816(c, a, b)                                                \
    asm volatile("mma.sync.aligned.m16n8k16.row.col.f32.f16.f16.f32 "    \
                 "{%0,%1,%2,%3}, {%4,%5,%6,%7}, {%8,%9}, {%0,%1,%2,%3};" \
                 : "+f"((c)[0]), "+f"((c)[1]), "+f"((c)[2]), "+f"((c)[3])\
                 : "r"((a)[0]), "r"((a)[1]), "r"((a)[2]), "r"((a)[3]),   \
                   "r"((b)[0]), "r"((b)[1]))

// ---------------------------------------------------------------------------
// Kernel 0: fp16 2-term splits of x and codebook (packed [h|l]) + |c|^2.
// One warp per 64-element row; lane handles 2 elements.
// ---------------------------------------------------------------------------
__global__ void __launch_bounds__(256)
split_kernel(const float* __restrict__ x, const float* __restrict__ cb)
{
    int gw   = (blockIdx.x * 256 + threadIdx.x) >> 5;
    int lane = threadIdx.x & 31;
    int e0   = lane * 2;

    if (gw < DIMC * BATCH) {
        int d = gw >> 9, b = gw & 511;
        float2 v = *(const float2*)(x + (size_t)b * CWDIM + d * EMB + e0);
        __half h0 = __float2half_rn(v.x);
        __half l0 = __float2half_rn(v.x - __half2float(h0));
        __half h1 = __float2half_rn(v.y);
        __half l1 = __float2half_rn(v.y - __half2float(h1));
        __half2* row = (__half2*)&g_x2[d][b][0];
        row[lane]      = __halves2half2(h0, h1);
        row[32 + lane] = __halves2half2(l0, l1);
    } else {
        int r = gw - DIMC * BATCH;                 // d*1024 + k
        float2 v = *(const float2*)(cb + (size_t)r * EMB + e0);
        __half h0 = __float2half_rn(v.x);
        __half l0 = __float2half_rn(v.x - __half2float(h0));
        __half h1 = __float2half_rn(v.y);
        __half l1 = __float2half_rn(v.y - __half2float(h1));
        __half2* row = (__half2*)(&g_c2[0][0][0] + (size_t)r * 128);
        row[lane]      = __halves2half2(h0, h1);
        row[32 + lane] = __halves2half2(l0, l1);
        float s = v.x * v.x + v.y * v.y;
        #pragma unroll
        for (int off = 16; off; off >>= 1)
            s += __shfl_xor_sync(0xffffffffu, s, off);
        if (lane == 0) g_bsq[r] = s;
    }
}

// ---------------------------------------------------------------------------
// Kernel 1: per (d, 128 rows, 128 codes) tile: dot = (hx+lx)(hc+lc) exactly,
// via 2 logical passes (aligned + k-half-swapped B) fused into one K loop.
// 256 threads = 8 warps (2M x 4N), warp tile 64x32. Fused one_hot zero +
// ncb/nema DECAY-init. Epilogue: per-row top-2 -> g_top.
// SMEM rows stride 272B (256 data + 16 pad) => conflict-free ldmatrix.
// ---------------------------------------------------------------------------
#define STRIDE   272
#define OFF_BSM  (128 * STRIDE)            // 34816
#define OFF_BSQ2 (2 * 128 * STRIDE)        // 69632
#define SMEM_REQ (OFF_BSQ2 + 512)          // 70144

__global__ void __launch_bounds__(256, 2)
gemm_kernel(const float* __restrict__ cbin, const float* __restrict__ ema,
            float* __restrict__ out)
{
    extern __shared__ char smp[];
    const uint32_t smA = smem_u32(smp);
    const uint32_t smB = smA + OFF_BSM;
    float* bsqs = (float*)(smp + OFF_BSQ2);

    const int t = threadIdx.x, warp = t >> 5, lane = t & 31;
    const int wm = warp >> 2, wn = warp & 3;
    const int mtc = blockIdx.x & 3, ntc = blockIdx.x >> 2;
    const int d  = blockIdx.y;
    const int b0 = mtc * 128, k0 = ntc * 128;
    const int blk = d * 32 + blockIdx.x;     // 0..2047

    // ---- fused output prep (fire-and-forget; overlaps other CTA's MMAs) ----
    {
        float4 z = make_float4(0.f, 0.f, 0.f, 0.f);
        float4* oh4 = (float4*)(out + OH_OFF);
        size_t base = (size_t)blk * 4096;
        #pragma unroll 4
        for (int it = 0; it < 16; ++it)
            oh4[base + t + it * 256] = z;

        const float4* cb4 = (const float4*)cbin;
        float4* ncb4 = (float4*)(out + NCB_OFF);
        size_t cb0 = (size_t)blk * 512;
        #pragma unroll
        for (int it = 0; it < 2; ++it) {
            float4 v = cb4[cb0 + t + it * 256];
            v.x *= 0.999f; v.y *= 0.999f; v.z *= 0.999f; v.w *= 0.999f;
            ncb4[cb0 + t + it * 256] = v;
        }
        if (t < 8) {
            const float4* em4 = (const float4*)ema;
            float4* ne4 = (float4*)(out + NEMA_OFF);
            size_t eb = (size_t)blk * 8 + t;
            float4 v = em4[eb];
            v.x *= 0.999f; v.y *= 0.999f; v.z *= 0.999f; v.w *= 0.999f;
            ne4[eb] = v;
        }
    }

    // ---- load A (x rows) and B (code rows), 256B each, + bsq ----
    #pragma unroll
    for (int it = 0; it < 8; ++it) {
        int idx = t + it * 256;          // 0..2047
        int row = idx >> 4, seg = idx & 15;
        uint4 va = *(const uint4*)(&g_x2[d][b0 + row][seg * 8]);
        *(uint4*)(smp + row * STRIDE + seg * 16) = va;
        uint4 vb = *(const uint4*)(&g_c2[d][k0 + row][seg * 8]);
        *(uint4*)(smp + OFF_BSM + row * STRIDE + seg * 16) = vb;
    }
    if (t < 128) bsqs[t] = g_bsq[d * BOOK + k0 + t];
    __syncthreads();

    // ---- MMA mainloop: 8 ksteps, each paired with aligned + swapped B ----
    float acc[4][4][4];
    #pragma unroll
    for (int i = 0; i < 4; ++i)
        #pragma unroll
        for (int j = 0; j < 4; ++j)
            #pragma unroll
            for (int q = 0; q < 4; ++q) acc[i][j][q] = 0.f;

    const int lr = (lane & 7) + ((lane >> 3) & 1) * 8;
    const int ka = ((lane >> 4) & 1) * 16;
    const int nr = (lane & 7) + ((lane >> 4) & 1) * 8;
    const int kb = ((lane >> 3) & 1) * 16;

    const uint32_t aBase = smA + (wm * 64 + lr) * STRIDE + ka;
    const uint32_t bBase = smB + (wn * 32 + nr) * STRIDE + kb;

    #pragma unroll
    for (int ks = 0; ks < 8; ++ks) {
        uint32_t af[4][4];
        #pragma unroll
        for (int mt = 0; mt < 4; ++mt)
            LDSM_X4(af[mt][0], af[mt][1], af[mt][2], af[mt][3],
                    aBase + mt * (16 * STRIDE) + ks * 32);
        #pragma unroll
        for (int v = 0; v < 2; ++v) {
            const int kk = (ks + v * 4) & 7;    // v=1: k-halves swapped
            uint32_t bf[4][2];
            #pragma unroll
            for (int np = 0; np < 2; ++np)
                LDSM_X4(bf[np * 2][0], bf[np * 2][1],
                        bf[np * 2 + 1][0], bf[np * 2 + 1][1],
                        bBase + np * (16 * STRIDE) + kk * 32);
            #pragma unroll
            for (int mt = 0; mt < 4; ++mt)
                #pragma unroll
                for (int nt = 0; nt < 4; ++nt)
                    MMA16816(acc[mt][nt], af[mt], bf[nt]);
        }
    }

    __syncthreads();   // A region about to be reused as sm_top
    float4* sm_top = (float4*)smp;   // [128 rows][4 wn]

    // ---- epilogue: per-row top-2 (dist = bsq - 2*dot) ----
    #pragma unroll
    for (int mt = 0; mt < 4; ++mt) {
        #pragma unroll
        for (int h = 0; h < 2; ++h) {
            int row = wm * 64 + mt * 16 + (lane >> 2) + h * 8;
            float b1 = 3.4e38f, b2 = 3.4e38f;
            int   k1 = 0;
            #pragma unroll
            for (int nt = 0; nt < 4; ++nt) {
                #pragma unroll
                for (int j = 0; j < 2; ++j) {
                    int col = wn * 32 + nt * 8 + (lane & 3) * 2 + j;
                    float dist = fmaf(-2.f, acc[mt][nt][h * 2 + j], bsqs[col]);
                    if (dist < b1) { b2 = b1; b1 = dist; k1 = k0 + col; }
                    else if (dist < b2) { b2 = dist; }
                }
            }
            #pragma unroll
            for (int off = 1; off <= 2; off <<= 1) {
                float ob1 = __shfl_xor_sync(0xffffffffu, b1, off);
                int   ok1 = __shfl_xor_sync(0xffffffffu, k1, off);
                float ob2 = __shfl_xor_sync(0xffffffffu, b2, off);
                if (ob1 < b1 || (ob1 == b1 && ok1 < k1)) {
                    b2 = fminf(ob2, b1); b1 = ob1; k1 = ok1;
                } else {
                    b2 = fminf(b2, ob1);
                }
            }
            if ((lane & 3) == 0)
                sm_top[row * 4 + wn] =
                    make_float4(b1, b2, __int_as_float(k1), 0.f);
        }
    }
    __syncthreads();

    if (t < 128) {
        float b1 = 3.4e38f, b2 = 3.4e38f;
        int   k1 = 0;
        #pragma unroll
        for (int w = 0; w < 4; ++w) {
            float4 e = sm_top[t * 4 + w];
            int ek = __float_as_int(e.z);
            if (e.x < b1 || (e.x == b1 && ek < k1)) {
                b2 = fminf(e.y, b1); b1 = e.x; k1 = ek;
            } else {
                b2 = fminf(b2, e.x);
            }
        }
        g_top[((size_t)(b0 + t) * DIMC + d) * 8 + ntc] =
            make_float4(b1, b2, __int_as_float(k1), 0.f);
    }
}

// ---------------------------------------------------------------------------
// Kernel 2: merge top-2 tiles -> argmin (exact fp32 repair when gap < TAU),
// then gather cw, set one_hot ones, EMA scatter-adds.
// One warp per (b,d).
// ---------------------------------------------------------------------------
__global__ void __launch_bounds__(256)
scatter_kernel(const float* __restrict__ x, const float* __restrict__ cb,
               const float* __restrict__ ema, float* __restrict__ out)
{
    const float GAINF = (float)(1.0 - 0.999);
    const float EPSF  = 1e-6f;
    float* cw   = out + CW_OFF;
    float* oh   = out + OH_OFF;
    float* ncb  = out + NCB_OFF;
    float* nema = out + NEMA_OFF;

    int b    = blockIdx.x;
    int warp = threadIdx.x >> 5;
    int lane = threadIdx.x & 31;

    #pragma unroll 1
    for (int dd = 0; dd < 8; ++dd) {
        int d = warp * 8 + dd;

        // merge the 8 N-tile top-2 entries
        float b1 = 3.4e38f, b2 = 3.4e38f;
        int   k1 = 0;
        if (lane < 8) {
            float4 e = g_top[((size_t)b * DIMC + d) * 8 + lane];
            b1 = e.x; b2 = e.y; k1 = __float_as_int(e.z);
        }
        #pragma unroll
        for (int off = 1; off <= 4; off <<= 1) {
            float ob1 = __shfl_xor_sync(0xffffffffu, b1, off);
            int   ok1 = __shfl_xor_sync(0xffffffffu, k1, off);
            float ob2 = __shfl_xor_sync(0xffffffffu, b2, off);
            if (ob1 < b1 || (ob1 == b1 && ok1 < k1)) {
                b2 = fminf(ob2, b1); b1 = ob1; k1 = ok1;
            } else {
                b2 = fminf(b2, ob1);
            }
        }
        float gap = __shfl_sync(0xffffffffu, b2 - b1, 0);
        int   k   = __shfl_sync(0xffffffffu, k1, 0);

        if (gap < TAU) {
            // exact fp32 re-argmin over all 1024 codes for this (b,d)
            const float* xr = x + (size_t)b * CWDIM + d * EMB;
            float bd = 3.4e38f;
            int   bk = 0;
            for (int i = 0; i < 32; ++i) {
                int kc = i * 32 + lane;
                const float* cp = cb + ((size_t)d * BOOK + kc) * EMB;
                float dot = 0.f;
                #pragma unroll
                for (int e = 0; e < EMB; ++e)
                    dot = fmaf(xr[e], cp[e], dot);
                float dist = fmaf(-2.f, dot, g_bsq[d * BOOK + kc]);
                if (dist < bd) { bd = dist; bk = kc; }
            }
            #pragma unroll
            for (int off = 16; off; off >>= 1) {
                float od = __shfl_xor_sync(0xffffffffu, bd, off);
                int   ok = __shfl_xor_sync(0xffffffffu, bk, off);
                if (od < bd || (od == bd && ok < bk)) { bd = od; bk = ok; }
            }
            k = bk;
        }

        float g = GAINF / (ema[d * BOOK + k] + EPSF);

        size_t co = ((size_t)d * BOOK + k) * EMB + 2 * lane;
        size_t xo = (size_t)b * CWDIM + d * EMB + 2 * lane;
        float2 c2 = *(const float2*)(cb + co);
        float2 x2 = *(const float2*)(x + xo);

        float2 w;
        w.x = x2.x + (c2.x - x2.x);
        w.y = x2.y + (c2.y - x2.y);
        *(float2*)(cw + xo) = w;

        atomicAdd(ncb + co,     g * x2.x);
        atomicAdd(ncb + co + 1, g * x2.y);

        if (lane == 0) {
            oh[(size_t)b * (DIMC * BOOK) + (size_t)d * BOOK + k] = 1.0f;
            atomicAdd(nema + d * BOOK + k, GAINF);
        }
    }
}

// ---------------------------------------------------------------------------
extern "C" void kernel_launch(void* const* d_in, const int* in_sizes, int n_in,
                              void* d_out, int out_size)
{
    (void)in_sizes; (void)n_in; (void)out_size;
    const float* x   = (const float*)d_in[0];
    const float* cb  = (const float*)d_in[1];
    const float* ema = (const float*)d_in[2];
    float* out = (float*)d_out;

    cudaFuncSetAttribute(gemm_kernel,
                         cudaFuncAttributeMaxDynamicSharedMemorySize, SMEM_REQ);

    split_kernel<<<12288, 256>>>(x, cb);
    dim3 grid(32, 64);   // 4 M-tiles x 8 N-tiles, 64 dims
    gemm_kernel<<<grid, 256, SMEM_REQ>>>(cb, ema, out);
    scatter_kernel<<<BATCH, 256>>>(x, cb, ema, out);
}